// round 2
// baseline (speedup 1.0000x reference)
#include <cuda_runtime.h>

// Quantum policy circuit: 14 qubits, 5 layers, batch 2048.
// One CTA per batch element; statevector SoA (re/im, 64KB each) in dynamic
// shared memory + 32KB inverse-ring-permutation table.
// Layer = 4 joint 2-gate smem passes + 1 single pass + 5 register-chunk gates
// with the CNOT ring fused into the chunk scatter. Layer 0 computed in closed
// form (product state); measurement fused into layer 4.

#define NQ 14
#define NL 5
#define NA 6
#define NSTATE 16384
#define NT 512
#define CHUNK 32     // NSTATE / NT

typedef unsigned long long ull;

// ---------- packed f32x2 helpers ----------
__device__ __forceinline__ ull pk(float lo, float hi) {
    ull r; asm("mov.b64 %0, {%1, %2};" : "=l"(r) : "f"(lo), "f"(hi)); return r;
}
__device__ __forceinline__ void upk(ull v, float& lo, float& hi) {
    asm("mov.b64 {%0, %1}, %2;" : "=f"(lo), "=f"(hi) : "l"(v));
}
__device__ __forceinline__ ull f2mul(ull a, ull b) {
    ull d; asm("mul.rn.f32x2 %0, %1, %2;" : "=l"(d) : "l"(a), "l"(b)); return d;
}
__device__ __forceinline__ ull f2fma(ull a, ull b, ull c) {
    ull d; asm("fma.rn.f32x2 %0, %1, %2, %3;" : "=l"(d) : "l"(a), "l"(b), "l"(c)); return d;
}

// Gate U = [[a, b], [-conj(b), conj(a)]], coefficients broadcast into f32x2.
struct GateP { ull ar, ai, br, bi, nai, nbr, nbi; };

__device__ __forceinline__ GateP mkgate(const float* u) {
    GateP g;
    g.ar  = pk(u[0], u[0]);   g.ai  = pk(u[1], u[1]);
    g.br  = pk(u[2], u[2]);   g.bi  = pk(u[3], u[3]);
    g.nai = pk(-u[1], -u[1]); g.nbr = pk(-u[2], -u[2]); g.nbi = pk(-u[3], -u[3]);
    return g;
}

// Apply gate to two independent amplitude pairs packed in f32x2 lanes.
// n0 = a*a0 + b*a1 ; n1 = -conj(b)*a0 + conj(a)*a1
__device__ __forceinline__ void apply2(const GateP& g, ull& a0r, ull& a0i,
                                       ull& a1r, ull& a1i) {
    ull n0r = f2fma(g.br,  a1r, f2fma(g.nbi, a1i, f2fma(g.nai, a0i, f2mul(g.ar,  a0r))));
    ull n0i = f2fma(g.bi,  a1r, f2fma(g.br,  a1i, f2fma(g.ai,  a0r, f2mul(g.ar,  a0i))));
    ull n1r = f2fma(g.ai,  a1i, f2fma(g.ar,  a1r, f2fma(g.nbi, a0i, f2mul(g.nbr, a0r))));
    ull n1i = f2fma(g.nai, a1r, f2fma(g.ar,  a1i, f2fma(g.bi,  a0r, f2mul(g.nbr, a0i))));
    a0r = n0r; a0i = n0i; a1r = n1r; a1i = n1i;
}

// 2x2 transpose of f32x2 lanes: (x0,x1),(y0,y1) -> (x0,y0),(x1,y1)
__device__ __forceinline__ void transp(ull a0, ull a1, ull& b0, ull& b1) {
    float x0, x1, y0, y1;
    upk(a0, x0, x1); upk(a1, y0, y1);
    b0 = pk(x0, y0); b1 = pk(x1, y1);
}

// ---------- joint two-qubit-pair butterfly pass (gates on wires Q1 and Q2) ----
template<int Q1, int Q2>
__device__ __forceinline__ void joint_pass(float* re, float* im,
                                           const float* su1, const float* su2,
                                           int tid) {
    const GateP g1 = mkgate(su1), g2 = mkgate(su2);
    #pragma unroll
    for (int k = 0; k < 8; ++k) {
        const int m  = tid + k * NT;                       // tuple id, 4096 tuples
        const int t1 = m & ((1 << Q1) - 1);
        const int t2 = (m >> Q1) & ((1 << (Q2 - Q1 - 1)) - 1);
        const int t3 = m >> (Q2 - 1);
        const int base = t1 | (t2 << (Q1 + 1)) | (t3 << (Q2 + 1));
        float v0r, v1r, v2r, v3r, v0i, v1i, v2i, v3i;
        if (Q1 == 0 && Q2 == 1) {
            const float4 r4 = *reinterpret_cast<const float4*>(re + base);
            const float4 i4 = *reinterpret_cast<const float4*>(im + base);
            v0r = r4.x; v1r = r4.y; v2r = r4.z; v3r = r4.w;
            v0i = i4.x; v1i = i4.y; v2i = i4.z; v3i = i4.w;
        } else {
            const int i1 = base + (1 << Q1);
            const int i2 = base + (1 << Q2);
            const int i3 = i1 + (1 << Q2);
            v0r = re[base]; v1r = re[i1]; v2r = re[i2]; v3r = re[i3];
            v0i = im[base]; v1i = im[i1]; v2i = im[i2]; v3i = im[i3];
        }
        // gate Q1 on pairs (v0,v1),(v2,v3)
        ull a0r = pk(v0r, v2r), a1r = pk(v1r, v3r);
        ull a0i = pk(v0i, v2i), a1i = pk(v1i, v3i);
        apply2(g1, a0r, a0i, a1r, a1i);
        // repack for gate Q2 on pairs (v0,v2),(v1,v3)
        ull b0r, b1r, b0i, b1i;
        transp(a0r, a1r, b0r, b1r);
        transp(a0i, a1i, b0i, b1i);
        apply2(g2, b0r, b0i, b1r, b1i);
        upk(b0r, v0r, v1r); upk(b1r, v2r, v3r);
        upk(b0i, v0i, v1i); upk(b1i, v2i, v3i);
        if (Q1 == 0 && Q2 == 1) {
            *reinterpret_cast<float4*>(re + base) = make_float4(v0r, v1r, v2r, v3r);
            *reinterpret_cast<float4*>(im + base) = make_float4(v0i, v1i, v2i, v3i);
        } else {
            const int i1 = base + (1 << Q1);
            const int i2 = base + (1 << Q2);
            const int i3 = i1 + (1 << Q2);
            re[base] = v0r; re[i1] = v1r; re[i2] = v2r; re[i3] = v3r;
            im[base] = v0i; im[i1] = v1i; im[i2] = v2i; im[i3] = v3i;
        }
    }
    __syncthreads();
}

// ---------- single-qubit pass, SIMD2 over two k-iterations -------------------
template<int Q>
__device__ __forceinline__ void single_pass(float* re, float* im,
                                            const float* su, int tid) {
    const GateP g = mkgate(su);
    #pragma unroll
    for (int k = 0; k < 8; ++k) {
        const int pa = tid + (2 * k) * NT;
        const int pb = pa + NT;
        const int i0a = ((pa >> Q) << (Q + 1)) | (pa & ((1 << Q) - 1));
        const int i1a = i0a + (1 << Q);
        const int i0b = ((pb >> Q) << (Q + 1)) | (pb & ((1 << Q) - 1));
        const int i1b = i0b + (1 << Q);
        ull a0r = pk(re[i0a], re[i0b]), a1r = pk(re[i1a], re[i1b]);
        ull a0i = pk(im[i0a], im[i0b]), a1i = pk(im[i1a], im[i1b]);
        apply2(g, a0r, a0i, a1r, a1i);
        float x, y;
        upk(a0r, x, y); re[i0a] = x; re[i0b] = y;
        upk(a1r, x, y); re[i1a] = x; re[i1b] = y;
        upk(a0i, x, y); im[i0a] = x; im[i0b] = y;
        upk(a1i, x, y); im[i1a] = x; im[i1b] = y;
    }
    __syncthreads();
}

__global__ void __launch_bounds__(NT, 1)
qcirc_kernel(const float* __restrict__ x,        // [B, 14]
             const float* __restrict__ iscale,   // [5, 28]
             const float* __restrict__ wts,      // [5, 28]
             const float* __restrict__ ascale,   // [6]
             const float* __restrict__ abias,    // [6]
             float* __restrict__ out)            // [B, 6]
{
    extern __shared__ float smem[];
    float* re = smem;                                     // [NSTATE]
    float* im = smem + NSTATE;                            // [NSTATE]
    unsigned short* permH = (unsigned short*)(smem + 2 * NSTATE);  // [NSTATE]

    __shared__ float s_u[NQ][4];                          // (ar, ai, br, bi)
    __shared__ float s_red[NT / 32][NA];

    const int tid = threadIdx.x;
    const int b = blockIdx.x;

    // ---- inverse ring permutation h = g^-1 (forward CNOT application).
    // Each thread builds only the entries it will scatter through (j=c*NT+tid),
    // so no barrier is needed for the table itself.
    #pragma unroll
    for (int c = 0; c < CHUNK; ++c) {
        const int j = c * NT + tid;
        int m = j;
        #pragma unroll
        for (int i2 = 0; i2 < NQ; ++i2)
            m ^= ((m >> i2) & 1) << ((i2 + 1) % NQ);
        permH[j] = (unsigned short)m;
    }

    float acc[NA];
    #pragma unroll
    for (int a = 0; a < NA; ++a) acc[a] = 0.0f;

    for (int l = 0; l < NL; ++l) {
        // ---- fused per-wire gate matrix: U = RY(beta) RZ(gamma) RY(alpha)
        if (tid < NQ) {
            const int i = tid;
            const float xi = x[b * NQ + i];
            const float* isl = iscale + l * 2 * NQ;
            const float* wl  = wts    + l * 2 * NQ;
            const float alpha = isl[i] * xi;
            const float gamma = isl[NQ + i] * xi + wl[i];
            const float beta  = wl[NQ + i];
            float sa, ca, sg, cg, sb, cb;
            sincosf(0.5f * alpha, &sa, &ca);
            sincosf(0.5f * gamma, &sg, &cg);
            sincosf(0.5f * beta,  &sb, &cb);
            const float cc = cb * ca, ss = sb * sa;
            const float cs = cb * sa, sc = sb * ca;
            s_u[i][0] =  cg * (cc - ss);   // ar
            s_u[i][1] = -sg * (cc + ss);   // ai
            s_u[i][2] = -cg * (cs + sc);   // br
            s_u[i][3] =  sg * (cs - sc);   // bi
        }
        __syncthreads();

        float cr[CHUNK], ci[CHUNK];

        if (l == 0) {
            // ---- layer 0 shortcut: pre-ring state is a tensor product.
            // amp(j) = prod_q ( bit_q(j) ? -conj(b_q) : a_q )
            float Pr = 1.0f, Pi = 0.0f;
            #pragma unroll
            for (int q = 0; q < 9; ++q) {
                const int bq = (tid >> q) & 1;
                const float fr = bq ? -s_u[q][2] : s_u[q][0];
                const float fi = bq ?  s_u[q][3] : s_u[q][1];
                const float nr = Pr * fr - Pi * fi;
                Pi = Pr * fi + Pi * fr;
                Pr = nr;
            }
            cr[0] = Pr; ci[0] = Pi;
            #pragma unroll
            for (int bb = 0; bb < 5; ++bb) {
                const float a0r = s_u[9 + bb][0], a0i = s_u[9 + bb][1];
                const float f1r = -s_u[9 + bb][2], f1i = s_u[9 + bb][3];
                #pragma unroll
                for (int c = 0; c < (1 << bb); ++c) {
                    const float tr = cr[c], ti = ci[c];
                    cr[c] = tr * a0r - ti * a0i;
                    ci[c] = tr * a0i + ti * a0r;
                    cr[c | (1 << bb)] = tr * f1r - ti * f1i;
                    ci[c | (1 << bb)] = tr * f1i + ti * f1r;
                }
            }
            // ring fused into scatter (first touch of smem state, no pre-barrier)
            #pragma unroll
            for (int c = 0; c < CHUNK; ++c) {
                const int d = permH[c * NT + tid];
                re[d] = cr[c]; im[d] = ci[c];
            }
            __syncthreads();
            continue;
        }

        // ---- smem passes for wires 0..8 (distant pairing limits conflicts)
        joint_pass<0, 1>(re, im, s_u[0], s_u[1], tid);
        joint_pass<2, 6>(re, im, s_u[2], s_u[6], tid);
        joint_pass<3, 7>(re, im, s_u[3], s_u[7], tid);
        joint_pass<4, 8>(re, im, s_u[4], s_u[8], tid);
        single_pass<5>(re, im, s_u[5], tid);

        // ---- register-chunk gather: j = c*512 + tid (wires 9..13 = c bits)
        #pragma unroll
        for (int c = 0; c < CHUNK; ++c) {
            cr[c] = re[c * NT + tid];
            ci[c] = im[c * NT + tid];
        }

        // ---- 5 register gates on wires 9..13 (chunk bits 0..4), SIMD2
        #pragma unroll
        for (int bb = 0; bb < 5; ++bb) {
            const GateP g = mkgate(s_u[9 + bb]);
            const int bit = 1 << bb;
            #pragma unroll
            for (int n = 0; n < 8; ++n) {
                const int na = 2 * n, nb = 2 * n + 1;
                const int ca = ((na & ~(bit - 1)) << 1) | (na & (bit - 1));
                const int cb = ((nb & ~(bit - 1)) << 1) | (nb & (bit - 1));
                ull a0r = pk(cr[ca], cr[cb]), a1r = pk(cr[ca + bit], cr[cb + bit]);
                ull a0i = pk(ci[ca], ci[cb]), a1i = pk(ci[ca + bit], ci[cb + bit]);
                apply2(g, a0r, a0i, a1r, a1i);
                upk(a0r, cr[ca], cr[cb]); upk(a1r, cr[ca + bit], cr[cb + bit]);
                upk(a0i, ci[ca], ci[cb]); upk(a1i, ci[ca + bit], ci[cb + bit]);
            }
        }

        if (l < NL - 1) {
            // ---- CNOT ring fused into scatter
            __syncthreads();   // all gathers done before any scatter
            #pragma unroll
            for (int c = 0; c < CHUNK; ++c) {
                const int d = permH[c * NT + tid];
                re[d] = cr[c]; im[d] = ci[c];
            }
            __syncthreads();
        } else {
            // ---- final layer: fuse ring + measurement (signs from dest index)
            #pragma unroll
            for (int c = 0; c < CHUNK; ++c) {
                const int d = permH[c * NT + tid];
                const float p = cr[c] * cr[c] + ci[c] * ci[c];
                #pragma unroll
                for (int a = 0; a < NA; ++a)
                    acc[a] += (d & (1 << a)) ? -p : p;
            }
        }
    }

    // ---- block reduction of <Z_a> ----------------------------------------
    #pragma unroll
    for (int a = 0; a < NA; ++a) {
        #pragma unroll
        for (int off = 16; off; off >>= 1)
            acc[a] += __shfl_xor_sync(0xffffffffu, acc[a], off);
    }
    const int lane = tid & 31, warp = tid >> 5;
    if (lane == 0) {
        #pragma unroll
        for (int a = 0; a < NA; ++a) s_red[warp][a] = acc[a];
    }
    __syncthreads();
    if (tid < NA) {
        float s = 0.0f;
        #pragma unroll
        for (int w = 0; w < NT / 32; ++w) s += s_red[w][tid];
        out[b * NA + tid] = s * ascale[tid] + abias[tid];
    }
}

extern "C" void kernel_launch(void* const* d_in, const int* in_sizes, int n_in,
                              void* d_out, int out_size) {
    const float* x      = (const float*)d_in[0];
    const float* iscale = (const float*)d_in[1];
    const float* wts    = (const float*)d_in[2];
    const float* ascale = (const float*)d_in[3];
    const float* abias  = (const float*)d_in[4];
    float* out = (float*)d_out;
    const int B = in_sizes[0] / NQ;

    const size_t shmem = (size_t)NSTATE * 2 * sizeof(float)
                       + (size_t)NSTATE * sizeof(unsigned short);  // 160 KB
    cudaFuncSetAttribute(qcirc_kernel,
                         cudaFuncAttributeMaxDynamicSharedMemorySize,
                         (int)shmem);
    qcirc_kernel<<<B, NT, shmem>>>(x, iscale, wts, ascale, abias, out);
}

// round 3
// speedup vs baseline: 1.2008x; 1.2008x over previous
#include <cuda_runtime.h>

// 14-qubit, 5-layer variational circuit, batch 2048. One CTA per batch
// element; state as interleaved complex float2[16384] (128 KB) in dynamic
// smem. Each layer = 3 register-resident rounds (local qubits 9-13 / 4-8 /
// 0-3) with XOR-swizzled conflict-free gathers/scatters; the CNOT ring
// (prefix-XOR linear map) is fused into round-1's gather addressing.
// Layer 0 in closed form (product state); measurement fused into layer 4.

#define NQ 14
#define NL 5
#define NA 6
#define NSTATE 16384
#define NT 512

typedef unsigned long long ull;

// ---------- packed f32x2 helpers ----------
__device__ __forceinline__ ull pk(float lo, float hi) {
    ull r; asm("mov.b64 %0, {%1, %2};" : "=l"(r) : "f"(lo), "f"(hi)); return r;
}
__device__ __forceinline__ void upk(ull v, float& lo, float& hi) {
    asm("mov.b64 {%0, %1}, %2;" : "=f"(lo), "=f"(hi) : "l"(v));
}
__device__ __forceinline__ ull f2mul(ull a, ull b) {
    ull d; asm("mul.rn.f32x2 %0, %1, %2;" : "=l"(d) : "l"(a), "l"(b)); return d;
}
__device__ __forceinline__ ull f2fma(ull a, ull b, ull c) {
    ull d; asm("fma.rn.f32x2 %0, %1, %2, %3;" : "=l"(d) : "l"(a), "l"(b), "l"(c)); return d;
}
__device__ __forceinline__ ull swpl(ull v) {        // swap f32x2 lanes
    float a, b; upk(v, a, b); return pk(b, a);
}

// Gate U = [[a, b], [-conj(b), conj(a)]], coefficients broadcast into f32x2.
struct Gate  { ull ar, ai, br, bi, nai, nbr, nbi; };
struct GateM { ull nai_ai, ai_nai, br_nbr; };       // mixed-lane variants

// Apply gate to two independent amplitude pairs packed in f32x2 lanes.
__device__ __forceinline__ void apply2(const Gate& g, ull& a0r, ull& a0i,
                                       ull& a1r, ull& a1i) {
    ull n0r = f2fma(g.br,  a1r, f2fma(g.nbi, a1i, f2fma(g.nai, a0i, f2mul(g.ar,  a0r))));
    ull n0i = f2fma(g.bi,  a1r, f2fma(g.br,  a1i, f2fma(g.ai,  a0r, f2mul(g.ar,  a0i))));
    ull n1r = f2fma(g.ai,  a1i, f2fma(g.ar,  a1r, f2fma(g.nbi, a0i, f2mul(g.nbr, a0r))));
    ull n1i = f2fma(g.nai, a1r, f2fma(g.ar,  a1i, f2fma(g.bi,  a0r, f2mul(g.nbr, a0i))));
    a0r = n0r; a0i = n0i; a1r = n1r; a1i = n1i;
}

// Gate on the SIMD pairing bit itself: butterfly between the two lanes of
// each pack, via lane-swapped operands and per-lane (mixed) coefficients.
__device__ __forceinline__ void apply_mixed(const Gate& g, const GateM& gm,
                                            ull& Pr, ull& Pi) {
    const ull Qr = swpl(Pr), Qi = swpl(Pi);
    ull Nr = f2fma(g.nbi,     Qi, f2fma(gm.br_nbr, Qr, f2fma(gm.nai_ai, Pi, f2mul(g.ar,      Pr))));
    ull Ni = f2fma(gm.br_nbr, Qi, f2fma(g.bi,      Qr, f2fma(g.ar,      Pi, f2mul(gm.ai_nai, Pr))));
    Pr = Nr; Pi = Ni;
}

// ---------- GF(2)-linear index maps (fold to constants for literal args) ----
// Forward ring (all 14 CNOTs): d[k]=j[0]^..^j[k] (k>=1), d[0]=parity(j[1..13])
__device__ constexpr int ringf(int x) {
    int y = x;
    y ^= y << 1; y ^= y << 2; y ^= y << 4; y ^= y << 8;
    y &= 0x3FFF;
    return (y & 0x3FFE) | (((y >> 13) ^ x) & 1);
}
__device__ constexpr int ringinv(int d) {
    int m  = (d ^ (d << 1)) & 0x3FFC;
    int m0 = ((d >> 13) ^ d) & 1;
    int m1 = ((d >> 13) ^ (d >> 1) ^ d) & 1;
    return m | m0 | (m1 << 1);
}
__device__ constexpr int swz(int j) {       // bits 1..3 ^= bits 5..7
    return j ^ (((j >> 5) & 7) << 1);
}

__global__ void __launch_bounds__(NT, 1)
qcirc_kernel(const float* __restrict__ x,        // [B, 14]
             const float* __restrict__ iscale,   // [5, 28]
             const float* __restrict__ wts,      // [5, 28]
             const float* __restrict__ ascale,   // [6]
             const float* __restrict__ abias,    // [6]
             float* __restrict__ out)            // [B, 6]
{
    extern __shared__ float2 st[];               // [NSTATE] 128 KB
    __shared__ Gate  s_g[NL][NQ];
    __shared__ GateM s_gm[NL][2];                // [.][0]: qubit13, [.][1]: qubit8
    __shared__ float s_u0[NQ][4];                // scalar copy for layer-0 product
    __shared__ float s_red[NT / 32][NA];

    const int t = threadIdx.x;
    const int b = blockIdx.x;

    // ---- build all layers' fused gate tables: U = RY(beta) RZ(gamma) RY(alpha)
    if (t < NL * NQ) {
        const int l = t / NQ, i = t % NQ;
        const float xi = x[b * NQ + i];
        const float* isl = iscale + l * 2 * NQ;
        const float* wl  = wts    + l * 2 * NQ;
        const float alpha = isl[i] * xi;
        const float gamma = isl[NQ + i] * xi + wl[i];
        const float beta  = wl[NQ + i];
        float sa, ca, sg, cg, sb, cb;
        sincosf(0.5f * alpha, &sa, &ca);
        sincosf(0.5f * gamma, &sg, &cg);
        sincosf(0.5f * beta,  &sb, &cb);
        const float cc = cb * ca, ss = sb * sa;
        const float cs = cb * sa, sc = sb * ca;
        const float ar =  cg * (cc - ss);
        const float ai = -sg * (cc + ss);
        const float br = -cg * (cs + sc);
        const float bi =  sg * (cs - sc);
        Gate gg;
        gg.ar = pk(ar, ar);   gg.ai = pk(ai, ai);
        gg.br = pk(br, br);   gg.bi = pk(bi, bi);
        gg.nai = pk(-ai, -ai); gg.nbr = pk(-br, -br); gg.nbi = pk(-bi, -bi);
        s_g[l][i] = gg;
        if (i == 13 || i == 8) {
            GateM gm;
            gm.nai_ai = pk(-ai, ai);
            gm.ai_nai = pk(ai, -ai);
            gm.br_nbr = pk(br, -br);
            s_gm[l][i == 13 ? 0 : 1] = gm;
        }
        if (l == 0) {
            s_u0[i][0] = ar; s_u0[i][1] = ai; s_u0[i][2] = br; s_u0[i][3] = bi;
        }
    }
    __syncthreads();

    // ---- per-thread layout bases (layer-invariant, GF2-linear pieces) ----
    const int g1   = swz(ringinv(t));                 // R1 gather base
    const int t2   = (t & 15) | ((t >> 4) << 9);      // R2 natural base
    const int s2   = swz(t2);                         // R2 scatter base
    const int b3   = swz(t << 5) >> 1;                // R3 float4 base (even)
    const int rt_m = ringf(t << 5);                   // measurement base

    float acc[NA];
    #pragma unroll
    for (int a = 0; a < NA; ++a) acc[a] = 0.0f;

    // ---- layer 0: pre-ring state is a product state; closed form ---------
    {
        float cr[32], ci[32];
        float Pr0 = 1.0f, Pi0 = 0.0f;
        #pragma unroll
        for (int q = 0; q < 9; ++q) {
            const int bq = (t >> q) & 1;
            const float fr = bq ? -s_u0[q][2] : s_u0[q][0];
            const float fi = bq ?  s_u0[q][3] : s_u0[q][1];
            const float nr = Pr0 * fr - Pi0 * fi;
            Pi0 = Pr0 * fi + Pi0 * fr;
            Pr0 = nr;
        }
        cr[0] = Pr0; ci[0] = Pi0;
        #pragma unroll
        for (int bb = 0; bb < 5; ++bb) {
            const float a0r = s_u0[9 + bb][0], a0i = s_u0[9 + bb][1];
            const float f1r = -s_u0[9 + bb][2], f1i = s_u0[9 + bb][3];
            #pragma unroll
            for (int c = 0; c < (1 << bb); ++c) {
                const float tr = cr[c], ti = ci[c];
                cr[c] = tr * a0r - ti * a0i;
                ci[c] = tr * a0i + ti * a0r;
                cr[c | (1 << bb)] = tr * f1r - ti * f1i;
                ci[c | (1 << bb)] = tr * f1i + ti * f1r;
            }
        }
        const int swt = swz(t);
        #pragma unroll
        for (int c = 0; c < 32; ++c)
            st[(c << 9) | swt] = make_float2(cr[c], ci[c]);
    }
    __syncthreads();

    // ---- layers 1..4: three register rounds each --------------------------
    ull Pr[16], Pi[16];
    #pragma unroll 1
    for (int l = 1; l < NL; ++l) {
        // ===== R1: local qubits 9..13 (ring of previous layer fused in) ====
        #pragma unroll
        for (int m = 0; m < 16; ++m) {
            const float2 A = st[g1 ^ swz(ringinv(m << 9))];
            const float2 B = st[g1 ^ swz(ringinv((m + 16) << 9))];
            Pr[m] = pk(A.x, B.x); Pi[m] = pk(A.y, B.y);
        }
        #pragma unroll
        for (int bb = 0; bb < 4; ++bb) {
            const Gate g = s_g[l][9 + bb];
            const int bit = 1 << bb;
            #pragma unroll
            for (int n = 0; n < 8; ++n) {
                const int lo = ((n & ~(bit - 1)) << 1) | (n & (bit - 1));
                apply2(g, Pr[lo], Pi[lo], Pr[lo | bit], Pi[lo | bit]);
            }
        }
        {
            const Gate g = s_g[l][13];
            const GateM gm = s_gm[l][0];
            #pragma unroll
            for (int m = 0; m < 16; ++m) apply_mixed(g, gm, Pr[m], Pi[m]);
        }
        __syncthreads();
        #pragma unroll
        for (int m = 0; m < 16; ++m) {
            float x0, x1, y0, y1;
            upk(Pr[m], x0, x1); upk(Pi[m], y0, y1);
            st[(m << 9) | t]        = make_float2(x0, y0);
            st[((m + 16) << 9) | t] = make_float2(x1, y1);
        }
        __syncthreads();

        // ===== R2: local qubits 4..8 =======================================
        #pragma unroll
        for (int m = 0; m < 16; ++m) {
            const float2 A = st[t2 ^ (m << 4)];
            const float2 B = st[t2 ^ ((m + 16) << 4)];
            Pr[m] = pk(A.x, B.x); Pi[m] = pk(A.y, B.y);
        }
        #pragma unroll
        for (int bb = 0; bb < 4; ++bb) {
            const Gate g = s_g[l][4 + bb];
            const int bit = 1 << bb;
            #pragma unroll
            for (int n = 0; n < 8; ++n) {
                const int lo = ((n & ~(bit - 1)) << 1) | (n & (bit - 1));
                apply2(g, Pr[lo], Pi[lo], Pr[lo | bit], Pi[lo | bit]);
            }
        }
        {
            const Gate g = s_g[l][8];
            const GateM gm = s_gm[l][1];
            #pragma unroll
            for (int m = 0; m < 16; ++m) apply_mixed(g, gm, Pr[m], Pi[m]);
        }
        __syncthreads();
        #pragma unroll
        for (int m = 0; m < 16; ++m) {
            float x0, x1, y0, y1;
            upk(Pr[m], x0, x1); upk(Pi[m], y0, y1);
            st[s2 ^ swz(m << 4)]        = make_float2(x0, y0);
            st[s2 ^ swz((m + 16) << 4)] = make_float2(x1, y1);
        }
        __syncthreads();

        // ===== R3: local qubits 0..3 (in-place per-thread, float4) =========
        float4* st4 = reinterpret_cast<float4*>(st);
        #pragma unroll
        for (int q = 0; q < 8; ++q) {
            const float4 F0 = st4[b3 ^ q];          // elements 2q, 2q+1
            const float4 F1 = st4[b3 ^ q ^ 8];      // elements 16+2q, 16+2q+1
            Pr[2 * q]     = pk(F0.x, F1.x); Pi[2 * q]     = pk(F0.y, F1.y);
            Pr[2 * q + 1] = pk(F0.z, F1.z); Pi[2 * q + 1] = pk(F0.w, F1.w);
        }
        #pragma unroll
        for (int bb = 0; bb < 4; ++bb) {
            const Gate g = s_g[l][bb];
            const int bit = 1 << bb;
            #pragma unroll
            for (int n = 0; n < 8; ++n) {
                const int lo = ((n & ~(bit - 1)) << 1) | (n & (bit - 1));
                apply2(g, Pr[lo], Pi[lo], Pr[lo | bit], Pi[lo | bit]);
            }
        }
        if (l < NL - 1) {
            #pragma unroll
            for (int q = 0; q < 8; ++q) {
                float r0, r1, i0, i1, r2, r3, i2, i3;
                upk(Pr[2 * q],     r0, r1); upk(Pi[2 * q],     i0, i1);
                upk(Pr[2 * q + 1], r2, r3); upk(Pi[2 * q + 1], i2, i3);
                st4[b3 ^ q]     = make_float4(r0, i0, r2, i2);
                st4[b3 ^ q ^ 8] = make_float4(r1, i1, r3, i3);
            }
            __syncthreads();
        } else {
            // ---- measurement fused with final ring (signs from ring index)
            #pragma unroll
            for (int m = 0; m < 16; ++m) {
                const ull Pp = f2fma(Pi[m], Pi[m], f2mul(Pr[m], Pr[m]));
                float p0, p1;
                upk(Pp, p0, p1);
                const int d0 = rt_m ^ ringf(m);
                const int d1 = rt_m ^ ringf(m | 16);
                #pragma unroll
                for (int a = 0; a < NA; ++a) {
                    acc[a] += ((d0 >> a) & 1) ? -p0 : p0;
                    acc[a] += ((d1 >> a) & 1) ? -p1 : p1;
                }
            }
        }
    }

    // ---- block reduction of <Z_a> ----------------------------------------
    #pragma unroll
    for (int a = 0; a < NA; ++a) {
        #pragma unroll
        for (int off = 16; off; off >>= 1)
            acc[a] += __shfl_xor_sync(0xffffffffu, acc[a], off);
    }
    const int lane = t & 31, warp = t >> 5;
    if (lane == 0) {
        #pragma unroll
        for (int a = 0; a < NA; ++a) s_red[warp][a] = acc[a];
    }
    __syncthreads();
    if (t < NA) {
        float s = 0.0f;
        #pragma unroll
        for (int w = 0; w < NT / 32; ++w) s += s_red[w][t];
        out[b * NA + t] = s * ascale[t] + abias[t];
    }
}

extern "C" void kernel_launch(void* const* d_in, const int* in_sizes, int n_in,
                              void* d_out, int out_size) {
    const float* x      = (const float*)d_in[0];
    const float* iscale = (const float*)d_in[1];
    const float* wts    = (const float*)d_in[2];
    const float* ascale = (const float*)d_in[3];
    const float* abias  = (const float*)d_in[4];
    float* out = (float*)d_out;
    const int B = in_sizes[0] / NQ;

    const size_t shmem = (size_t)NSTATE * sizeof(float2);   // 128 KB
    cudaFuncSetAttribute(qcirc_kernel,
                         cudaFuncAttributeMaxDynamicSharedMemorySize,
                         (int)shmem);
    qcirc_kernel<<<B, NT, shmem>>>(x, iscale, wts, ascale, abias, out);
}